// round 15
// baseline (speedup 1.0000x reference)
#include <cuda_runtime.h>
#include <cuda_fp16.h>
#include <math.h>
#include <stdint.h>
#include <string.h>

#define HH 28
#define WW 28
#define P 784
#define NB 32768
#define NTILES 14             // N-tiles of 56 output pixels (= 2 image rows each)
#define NT_W 56
#define AP 792                // A smem pitch in halves (792*2B: 99 16B-slots/row, 99%8==3 -> ldmatrix conflict-free)
#define BP 248                // B smem pitch in halves (31 slots/row, odd -> conflict-free)
#define KTILE 240             // max K per B chunk (bands wider than this loop twice; rare)
#define A_BYTES (128 * AP * 2)          // 202752
#define B_OFF A_BYTES
#define DSMEM (A_BYTES + NT_W * BP * 2) // 202752 + 27776 = 230528
#define THREADS 256

// Dense M^T (row p = output pixel, col q = input pixel), fp16, rebuilt per launch.
__device__ __align__(16) __half g_Bh[P * P];
__device__ int g_krange[NTILES * 2];    // per N-tile: [kmin, kmax] over live q

__device__ __forceinline__ uint32_t smem_u32(const void* p) {
    uint32_t a;
    asm("{ .reg .u64 t; cvta.to.shared.u64 t, %1; cvt.u32.u64 %0, t; }" : "=r"(a) : "l"(p));
    return a;
}
__device__ __forceinline__ void ldsm_x4(uint32_t* r, uint32_t addr) {
    asm volatile("ldmatrix.sync.aligned.m8n8.x4.shared.b16 {%0,%1,%2,%3}, [%4];"
                 : "=r"(r[0]), "=r"(r[1]), "=r"(r[2]), "=r"(r[3]) : "r"(addr));
}
__device__ __forceinline__ void ldsm_x2(uint32_t* r, uint32_t addr) {
    asm volatile("ldmatrix.sync.aligned.m8n8.x2.shared.b16 {%0,%1}, [%2];"
                 : "=r"(r[0]), "=r"(r[1]) : "r"(addr));
}
__device__ __forceinline__ void mma16816(float* c, const uint32_t* a,
                                         uint32_t b0, uint32_t b1) {
    asm volatile(
        "mma.sync.aligned.m16n8k16.row.col.f32.f16.f16.f32 "
        "{%0,%1,%2,%3}, {%4,%5,%6,%7}, {%8,%9}, {%0,%1,%2,%3};"
        : "+f"(c[0]), "+f"(c[1]), "+f"(c[2]), "+f"(c[3])
        : "r"(a[0]), "r"(a[1]), "r"(a[2]), "r"(a[3]), "r"(b0), "r"(b1));
}

// ------------------------- pre-kernels -------------------------
__global__ void zero_kernel() {
    uint4* b4 = (uint4*)g_Bh;
    const uint4 z = make_uint4(0u, 0u, 0u, 0u);
    const int n4 = P * P * 2 / 16;
    for (int i = blockIdx.x * blockDim.x + threadIdx.x; i < n4; i += gridDim.x * blockDim.x)
        b4[i] = z;
    if (blockIdx.x == 0 && threadIdx.x < NTILES) {
        g_krange[2 * threadIdx.x + 0] = 0x3FFFFFFF;
        g_krange[2 * threadIdx.x + 1] = 0;
    }
}

__global__ void scatter_kernel(const float* __restrict__ pos2d,
                               const float* __restrict__ weight) {
    int p = blockIdx.x * blockDim.x + threadIdx.x;
    if (p >= P) return;
    float px = pos2d[2 * p + 0];
    float py = pos2d[2 * p + 1];
    float sw = fmaxf(weight[p], 0.0f);
    float ce0 = rintf(px);   // round-half-to-even == jnp.round
    float ce1 = rintf(py);
    int t = p / NT_W;
    int qmin = 0x3FFFFFFF;
    int qmax = 0;
    for (int i0 = -2; i0 <= 2; i0++) {
        for (int i1 = -2; i1 <= 2; i1++) {
            float cr0 = ce0 + (float)i0;
            float cr1 = ce1 + (float)i1;
            int c0 = (int)cr0;
            int c1 = (int)cr1;
            if (c0 < 0 || c0 >= HH || c1 < 0 || c1 >= WW) continue;  // OOB stays 0
            float d0 = cr0 - px;
            float d1 = cr1 - py;
            float wv = expf(-0.5f * (d0 * d0 + d1 * d1)) * sw;
            int q = c0 * WW + c1;
            g_Bh[(size_t)p * P + q] = __float2half(wv);
            qmin = min(qmin, q);
            qmax = max(qmax, q);
        }
    }
    atomicMin(&g_krange[2 * t + 0], qmin);
    atomicMax(&g_krange[2 * t + 1], qmax);
}

// ------------------------- GEMM kernel (mma.sync HMMA) -------------------------
__global__ __launch_bounds__(THREADS, 1) void gemm_kernel(const float* __restrict__ xg,
                                                          float* __restrict__ outg) {
    extern __shared__ __align__(16) char dsm[];
    __half* As = (__half*)dsm;                  // 128 x 784 (pitch 792), resident
    __half* Bs = (__half*)(dsm + B_OFF);        // 56 x <=240 (pitch 248), per tile

    const int tid = threadIdx.x;
    const int wid = tid >> 5;
    const int lane = tid & 31;
    const int b0 = blockIdx.x * 128;

    // ---- Load A: 128 batches x 784, fp32 -> fp16 (rounding subsumes 1e-8 clamp) ----
    {
        const float4* x4 = (const float4*)xg + (size_t)b0 * 196;
        for (int idx = tid; idx < 128 * 196; idx += THREADS) {
            float4 f = x4[idx];
            const int r = idx / 196;
            const int c = idx - r * 196;
            __half2 h0 = __floats2half2_rn(f.x, f.y);
            __half2 h1 = __floats2half2_rn(f.z, f.w);
            uint32_t u0, u1;
            memcpy(&u0, &h0, 4);
            memcpy(&u1, &h1, 4);
            *(uint2*)(As + r * AP + c * 4) = make_uint2(u0, u1);
        }
    }
    __syncthreads();

    // ---- Per-lane ldmatrix base addresses ----
    // A (m16k16 as 4 8x8 mats): lanes 0-7 rows wm+0-7 @k, 8-15 rows wm+8-15 @k,
    //                           16-23 rows wm+0-7 @k+8, 24-31 rows wm+8-15 @k+8
    const int a_row = (wid << 4) + (lane & 7) + (((lane >> 3) & 1) << 3);
    const int a_k = (lane >> 4) << 3;
    const uint32_t a_base = smem_u32(As) + (uint32_t)(a_row * AP + a_k) * 2u;
    // B x4 group j covers n-frags {2j,2j+1}: lanes 0-7: n 16j+0-7 @k, 8-15: same n @k+8,
    //                                        16-23: n 16j+8-15 @k, 24-31: same @k+8
    const int b_n = ((lane >> 4) << 3) + (lane & 7);
    const int b_k = ((lane >> 3) & 1) << 3;
    const uint32_t b_smem = smem_u32(Bs);
    const uint32_t b_base0 = b_smem + (uint32_t)((0 + b_n) * BP + b_k) * 2u;
    const uint32_t b_base1 = b_smem + (uint32_t)((16 + b_n) * BP + b_k) * 2u;
    const uint32_t b_base2 = b_smem + (uint32_t)((32 + b_n) * BP + b_k) * 2u;
    // x2 (frag 6, n 48-55): lanes 0-7: n 48+0-7 @k, 8-15: same @k+8 (lanes>=16 ignored)
    const uint32_t b_base3 = b_smem + (uint32_t)((48 + (lane & 7)) * BP + b_k) * 2u;

    for (int t = 0; t < NTILES; t++) {
        float cacc[28];
        #pragma unroll
        for (int i = 0; i < 28; i++) cacc[i] = 0.0f;

        const int kmin = g_krange[2 * t + 0];
        const int kmax = g_krange[2 * t + 1];
        const int k0 = kmin & ~15;
        const int k1 = (kmax < kmin) ? k0 : ((kmax & ~15) + 16);
        const int p0 = t * NT_W;

        for (int kb = k0; kb < k1; kb += KTILE) {
            const int Kt = min(KTILE, k1 - kb);
            const int Kt8 = Kt >> 3;
            __syncthreads();   // previous B tile fully consumed
            // Load B chunk: Mt[p0..p0+55][kb..kb+Kt) from global (L2-resident)
            for (int idx = tid; idx < NT_W * Kt8; idx += THREADS) {
                const int n = idx / Kt8;
                const int c = idx - n * Kt8;
                uint4 v = *(const uint4*)((const char*)g_Bh
                                          + ((size_t)(p0 + n) * P + (size_t)kb) * 2 + (size_t)c * 16);
                *(uint4*)((char*)Bs + (size_t)n * (BP * 2) + (size_t)c * 16) = v;
            }
            __syncthreads();

            const int nks = Kt >> 4;
            uint32_t aaddr = a_base + (uint32_t)kb * 2u;
            uint32_t koff = 0u;
            #pragma unroll 1
            for (int ks = 0; ks < nks; ks++) {
                uint32_t a[4];
                uint32_t bb[14];
                ldsm_x4(a, aaddr);
                ldsm_x4(bb + 0, b_base0 + koff);
                ldsm_x4(bb + 4, b_base1 + koff);
                ldsm_x4(bb + 8, b_base2 + koff);
                ldsm_x2(bb + 12, b_base3 + koff);
                #pragma unroll
                for (int j = 0; j < 7; j++)
                    mma16816(cacc + 4 * j, a, bb[2 * j], bb[2 * j + 1]);
                aaddr += 32u;
                koff += 32u;
            }
        }

        // ---- Epilogue: direct f32 stores ----
        const int row0 = b0 + (wid << 4) + (lane >> 2);
        const int colb = p0 + ((lane & 3) << 1);
        #pragma unroll
        for (int j = 0; j < 7; j++) {
            float2 v01 = make_float2(cacc[4 * j + 0], cacc[4 * j + 1]);
            float2 v23 = make_float2(cacc[4 * j + 2], cacc[4 * j + 3]);
            *(float2*)(outg + (size_t)row0 * P + colb + 8 * j) = v01;
            *(float2*)(outg + (size_t)(row0 + 8) * P + colb + 8 * j) = v23;
        }
    }
}

extern "C" void kernel_launch(void* const* d_in, const int* in_sizes, int n_in,
                              void* d_out, int out_size) {
    const float* x      = (const float*)d_in[0];  // (32768,1,28,28) f32
    const float* pos2d  = (const float*)d_in[1];  // (28,28,2) f32
    const float* weight = (const float*)d_in[2];  // (28,28) f32
    float* out = (float*)d_out;

    cudaFuncSetAttribute(gemm_kernel, cudaFuncAttributeMaxDynamicSharedMemorySize, DSMEM);

    zero_kernel<<<160, 256>>>();
    scatter_kernel<<<4, 256>>>(pos2d, weight);
    gemm_kernel<<<NB / 128, THREADS, DSMEM>>>(x, out);
}